// round 1
// baseline (speedup 1.0000x reference)
#include <cuda_runtime.h>
#include <cuda_bf16.h>

// dense_image_warp: out[b,y,x,c] = bilinear(image, (y,x) - flow[b,y,x,:])
// image: [B,H,W,C] f32, flow: [B,H,W,2] f32 (dy, dx). TFA clamping:
// floor clipped to [0, size-2], alpha clipped to [0,1].

static constexpr int B = 8;
static constexpr int H = 1024;
static constexpr int W = 768;
static constexpr int C = 3;

__global__ __launch_bounds__(256)
void warp_kernel(const float* __restrict__ image,
                 const float2* __restrict__ flow,
                 float* __restrict__ out)
{
    const int npix = B * H * W;
    int pix = blockIdx.x * blockDim.x + threadIdx.x;
    if (pix >= npix) return;

    // decompose pix -> (b, y, x)
    int x = pix % W;
    int t = pix / W;
    int y = t % H;
    int b = t / H;

    float2 f = flow[pix];           // f.x = dy, f.y = dx
    float qy = (float)y - f.x;
    float qx = (float)x - f.y;

    float y0f = fminf(fmaxf(floorf(qy), 0.0f), (float)(H - 2));
    float x0f = fminf(fmaxf(floorf(qx), 0.0f), (float)(W - 2));
    float ay  = fminf(fmaxf(qy - y0f, 0.0f), 1.0f);
    float ax  = fminf(fmaxf(qx - x0f, 0.0f), 1.0f);

    int y0 = (int)y0f;
    int x0 = (int)x0f;

    const float* p = image + ((size_t)((b * H + y0) * W + x0)) * C;  // top-left pixel
    const float* q = p + (size_t)W * C;                              // bottom-left pixel

    // Batch all 12 loads up front for MLP.
    float tl0 = __ldg(p + 0), tl1 = __ldg(p + 1), tl2 = __ldg(p + 2);
    float tr0 = __ldg(p + 3), tr1 = __ldg(p + 4), tr2 = __ldg(p + 5);
    float bl0 = __ldg(q + 0), bl1 = __ldg(q + 1), bl2 = __ldg(q + 2);
    float br0 = __ldg(q + 3), br1 = __ldg(q + 4), br2 = __ldg(q + 5);

    float top0 = tl0 + ax * (tr0 - tl0);
    float top1 = tl1 + ax * (tr1 - tl1);
    float top2 = tl2 + ax * (tr2 - tl2);
    float bot0 = bl0 + ax * (br0 - bl0);
    float bot1 = bl1 + ax * (br1 - bl1);
    float bot2 = bl2 + ax * (br2 - bl2);

    float* o = out + (size_t)pix * C;
    o[0] = top0 + ay * (bot0 - top0);
    o[1] = top1 + ay * (bot1 - top1);
    o[2] = top2 + ay * (bot2 - top2);
}

extern "C" void kernel_launch(void* const* d_in, const int* in_sizes, int n_in,
                              void* d_out, int out_size)
{
    const float*  image = (const float*)d_in[0];
    const float2* flow  = (const float2*)d_in[1];
    float*        out   = (float*)d_out;

    const int npix = B * H * W;
    const int threads = 256;
    const int blocks = (npix + threads - 1) / threads;
    warp_kernel<<<blocks, threads>>>(image, flow, out);
}

// round 2
// speedup vs baseline: 1.1777x; 1.1777x over previous
#include <cuda_runtime.h>
#include <cuda_bf16.h>

// dense_image_warp: out[b,y,x,c] = bilinear(image, (y,x) - flow[b,y,x,:])
// image: [B,H,W,C] f32, flow: [B,H,W,2] f32 (dy, dx). TFA clamping:
// floor clipped to [0, size-2], alpha clipped to [0,1].

static constexpr int B = 8;
static constexpr int H = 1024;
static constexpr int W = 768;
static constexpr int C = 3;
static constexpr int ROW_STRIDE = W * C;       // 2304 floats, %4 == 0 -> same alignment both rows

__device__ __forceinline__ float sel4(float v0, float v1, float v2, float v3, int r) {
    return r == 0 ? v0 : (r == 1 ? v1 : (r == 2 ? v2 : v3));
}

__global__ __launch_bounds__(256)
void warp_kernel(const float* __restrict__ image,
                 const float2* __restrict__ flow,
                 float4* __restrict__ out4)
{
    __shared__ float sbuf[256 * C];   // 768 floats

    const int tid = threadIdx.x;
    const int pix = blockIdx.x * 256 + tid;     // grid is exact: 24576*256 == B*H*W

    // decompose pix -> (b, y, x)
    int x = pix % W;
    int t = pix / W;
    int y = t % H;
    int b = t / H;

    float2 f = flow[pix];           // f.x = dy, f.y = dx
    float qy = (float)y - f.x;
    float qx = (float)x - f.y;

    float y0f = fminf(fmaxf(floorf(qy), 0.0f), (float)(H - 2));
    float x0f = fminf(fmaxf(floorf(qx), 0.0f), (float)(W - 2));
    float ay  = fminf(fmaxf(qy - y0f, 0.0f), 1.0f);
    float ax  = fminf(fmaxf(qx - x0f, 0.0f), 1.0f);

    int y0 = (int)y0f;
    int x0 = (int)x0f;

    // top-left float index; 6 consecutive floats cover tl(3)+tr(3)
    int pidx = ((b * H + y0) * W + x0) * C;
    int base = pidx & ~3;            // 16B-aligned float index
    int r    = pidx & 3;

    const float4* imgT = (const float4*)(image + base);
    const float4* imgB = (const float4*)(image + base + ROW_STRIDE);

    // Batch all loads up front for MLP. Over-read is provably in-bounds:
    // max touched index is pidx+8 with pidx%4==3, which lands exactly on the
    // last image element in the worst case.
    float4 ta = __ldg(imgT + 0);
    float4 tb = __ldg(imgT + 1);
    float4 ba = __ldg(imgB + 0);
    float4 bb = __ldg(imgB + 1);
    float  tc = 0.0f, bc = 0.0f;
    if (r == 3) {
        tc = __ldg(image + base + 8);
        bc = __ldg(image + base + ROW_STRIDE + 8);
    }

    // Extract the 6 taps per row according to misalignment r.
    float tl0 = sel4(ta.x, ta.y, ta.z, ta.w, r);
    float tl1 = sel4(ta.y, ta.z, ta.w, tb.x, r);
    float tl2 = sel4(ta.z, ta.w, tb.x, tb.y, r);
    float tr0 = sel4(ta.w, tb.x, tb.y, tb.z, r);
    float tr1 = sel4(tb.x, tb.y, tb.z, tb.w, r);
    float tr2 = sel4(tb.y, tb.z, tb.w, tc,   r);

    float bl0 = sel4(ba.x, ba.y, ba.z, ba.w, r);
    float bl1 = sel4(ba.y, ba.z, ba.w, bb.x, r);
    float bl2 = sel4(ba.z, ba.w, bb.x, bb.y, r);
    float br0 = sel4(ba.w, bb.x, bb.y, bb.z, r);
    float br1 = sel4(bb.x, bb.y, bb.z, bb.w, r);
    float br2 = sel4(bb.y, bb.z, bb.w, bc,   r);

    float top0 = tl0 + ax * (tr0 - tl0);
    float top1 = tl1 + ax * (tr1 - tl1);
    float top2 = tl2 + ax * (tr2 - tl2);
    float bot0 = bl0 + ax * (br0 - bl0);
    float bot1 = bl1 + ax * (br1 - bl1);
    float bot2 = bl2 + ax * (br2 - bl2);

    sbuf[tid * 3 + 0] = top0 + ay * (bot0 - top0);
    sbuf[tid * 3 + 1] = top1 + ay * (bot1 - top1);
    sbuf[tid * 3 + 2] = top2 + ay * (bot2 - top2);

    __syncthreads();

    // Coalesced float4 stores: 192 threads cover 768 floats.
    if (tid < 192) {
        const float4* s4 = (const float4*)sbuf;
        out4[blockIdx.x * 192 + tid] = s4[tid];
    }
}

extern "C" void kernel_launch(void* const* d_in, const int* in_sizes, int n_in,
                              void* d_out, int out_size)
{
    const float*  image = (const float*)d_in[0];
    const float2* flow  = (const float2*)d_in[1];
    float4*       out4  = (float4*)d_out;

    const int npix = B * H * W;                 // 6,291,456
    const int threads = 256;
    const int blocks = npix / threads;          // 24,576 exact
    warp_kernel<<<blocks, threads>>>(image, flow, out4);
}

// round 3
// speedup vs baseline: 1.1807x; 1.0026x over previous
#include <cuda_runtime.h>
#include <cuda_bf16.h>

// dense_image_warp: out[b,y,x,c] = bilinear(image, (y,x) - flow[b,y,x,:])
// image: [B,H,W,C] f32, flow: [B,H,W,2] f32 (dy, dx). TFA clamping:
// floor clipped to [0, size-2], alpha clipped to [0,1].
//
// Block = 512 threads covering a 128(x) x 4(y) pixel tile. The y-tiling makes
// pixel (x,y+1)'s top-row taps hit the same L1 lines as pixel (x,y)'s
// bottom-row taps (same SM, same time window), cutting L2 image traffic.

static constexpr int B = 8;
static constexpr int H = 1024;
static constexpr int W = 768;
static constexpr int C = 3;
static constexpr int ROW_STRIDE = W * C;   // 2304 floats, %4==0 -> both rows share alignment

static constexpr int TX = 128;             // tile x
static constexpr int TY = 4;               // tile y
static constexpr int THREADS = TX * TY;    // 512

__device__ __forceinline__ float sel4(float v0, float v1, float v2, float v3, int r) {
    return r == 0 ? v0 : (r == 1 ? v1 : (r == 2 ? v2 : v3));
}

__global__ __launch_bounds__(THREADS)
void warp_kernel(const float* __restrict__ image,
                 const float2* __restrict__ flow,
                 float4* __restrict__ out4)
{
    __shared__ float sbuf[THREADS * C];    // 6 KB

    const int tid = threadIdx.x;
    const int xl  = tid & (TX - 1);        // 0..127
    const int ty  = tid >> 7;              // 0..3

    const int x = blockIdx.x * TX + xl;
    const int y = blockIdx.y * TY + ty;
    const int b = blockIdx.z;

    const int pix = (b * H + y) * W + x;

    float2 f = flow[pix];                  // f.x = dy, f.y = dx
    float qy = (float)y - f.x;
    float qx = (float)x - f.y;

    float y0f = fminf(fmaxf(floorf(qy), 0.0f), (float)(H - 2));
    float x0f = fminf(fmaxf(floorf(qx), 0.0f), (float)(W - 2));
    float ay  = fminf(fmaxf(qy - y0f, 0.0f), 1.0f);
    float ax  = fminf(fmaxf(qx - x0f, 0.0f), 1.0f);

    int y0 = (int)y0f;
    int x0 = (int)x0f;

    // top-left float index; 6 consecutive floats cover tl(3)+tr(3)
    int pidx = ((b * H + y0) * W + x0) * C;
    int base = pidx & ~3;                  // 16B-aligned float index
    int r    = pidx & 3;

    const float4* imgT = (const float4*)(image + base);
    const float4* imgB = (const float4*)(image + base + ROW_STRIDE);

    // Batch all loads up front for MLP. Worst-case touched index (r==3) is
    // exactly the last image element.
    float4 ta = __ldg(imgT + 0);
    float4 tb = __ldg(imgT + 1);
    float4 ba = __ldg(imgB + 0);
    float4 bb = __ldg(imgB + 1);
    float  tc = 0.0f, bc = 0.0f;
    if (r == 3) {
        tc = __ldg(image + base + 8);
        bc = __ldg(image + base + ROW_STRIDE + 8);
    }

    // Extract the 6 taps per row according to misalignment r.
    float tl0 = sel4(ta.x, ta.y, ta.z, ta.w, r);
    float tl1 = sel4(ta.y, ta.z, ta.w, tb.x, r);
    float tl2 = sel4(ta.z, ta.w, tb.x, tb.y, r);
    float tr0 = sel4(ta.w, tb.x, tb.y, tb.z, r);
    float tr1 = sel4(tb.x, tb.y, tb.z, tb.w, r);
    float tr2 = sel4(tb.y, tb.z, tb.w, tc,   r);

    float bl0 = sel4(ba.x, ba.y, ba.z, ba.w, r);
    float bl1 = sel4(ba.y, ba.z, ba.w, bb.x, r);
    float bl2 = sel4(ba.z, ba.w, bb.x, bb.y, r);
    float br0 = sel4(ba.w, bb.x, bb.y, bb.z, r);
    float br1 = sel4(bb.x, bb.y, bb.z, bb.w, r);
    float br2 = sel4(bb.y, bb.z, bb.w, bc,   r);

    float top0 = tl0 + ax * (tr0 - tl0);
    float top1 = tl1 + ax * (tr1 - tl1);
    float top2 = tl2 + ax * (tr2 - tl2);
    float bot0 = bl0 + ax * (br0 - bl0);
    float bot1 = bl1 + ax * (br1 - bl1);
    float bot2 = bl2 + ax * (br2 - bl2);

    sbuf[tid * 3 + 0] = top0 + ay * (bot0 - top0);
    sbuf[tid * 3 + 1] = top1 + ay * (bot1 - top1);
    sbuf[tid * 3 + 2] = top2 + ay * (bot2 - top2);

    __syncthreads();

    // Coalesced float4 stores. Per sub-row: 128 px * 3 = 384 floats = 96 float4.
    // Thread t < 384 stores float4 t; sub-row = t/96, idx-in-row = t%96.
    if (tid < TY * 96) {
        int sr = tid / 96;                 // sub-row 0..3
        int i  = tid - sr * 96;
        int yo = blockIdx.y * TY + sr;
        // float4 base index of this output row segment (provably %1 exact):
        // ((b*H+yo)*W + blockIdx.x*TX)*3 / 4 = (b*H+yo)*576 + blockIdx.x*96
        int obase = (b * H + yo) * 576 + blockIdx.x * 96;
        const float4* s4 = (const float4*)sbuf;
        out4[obase + i] = s4[tid];
    }
}

extern "C" void kernel_launch(void* const* d_in, const int* in_sizes, int n_in,
                              void* d_out, int out_size)
{
    const float*  image = (const float*)d_in[0];
    const float2* flow  = (const float2*)d_in[1];
    float4*       out4  = (float4*)d_out;

    dim3 grid(W / TX, H / TY, B);          // (6, 256, 8) exact
    warp_kernel<<<grid, THREADS>>>(image, flow, out4);
}